// round 1
// baseline (speedup 1.0000x reference)
#include <cuda_runtime.h>
#include <math.h>

// Problem constants (fixed by the reference setup_inputs)
#define NB 16
#define NA 5
#define NCLS 20
#define NH 64
#define NW 64
#define MAXGT 50
#define CH (NA * (5 + NCLS))       // 125
#define CELLS_PER_B (NA * NH * NW) // 20480
#define SPLANE (NH * NW)           // 4096
#define SIL_T 0.6f

struct GtMeta {
    int flat;
    int valid;
    int tcls;
    float txv, tyv, twv, thv, iou_best;
};

__device__ double g_acc;
__device__ float g_boxes[NB][MAXGT][5]; // x1,y1,x2,y2,area (compacted valid GTs)
__device__ int   g_cnt[NB];
__device__ GtMeta g_meta[NB][MAXGT];

__device__ __forceinline__ float sigm(float v) { return 1.0f / (1.0f + expf(-v)); }

__device__ __forceinline__ float iou_corners(float px1, float py1, float px2, float py2, float parea,
                                             float bx1, float by1, float bx2, float by2, float barea) {
    float iw = fmaxf(fminf(px2, bx2) - fmaxf(px1, bx1), 0.0f);
    float ih = fmaxf(fminf(py2, by2) - fmaxf(py1, by1), 0.0f);
    float inter = iw * ih;
    float uni = parea + barea - inter;
    return uni > 0.0f ? inter / uni : 0.0f;
}

// ---------------------------------------------------------------------------
// Pass A: per-batch GT preprocessing (one thread per batch). Also zeros g_acc.
// ---------------------------------------------------------------------------
__global__ void pass_a(const float* __restrict__ out, const float* __restrict__ tgt,
                       const float* __restrict__ anchors) {
    int b = threadIdx.x;
    if (b == 0) g_acc = 0.0;
    if (b >= NB) return;

    int cnt = 0;
    for (int g = 0; g < MAXGT; ++g) {
        const float* t = tgt + (b * MAXGT + g) * 5;
        float cls = t[0], t1 = t[1], t2 = t[2], t3 = t[3], t4 = t[4];
        int valid = (t1 > 0.0f);

        GtMeta m;
        m.valid = valid; m.flat = -1; m.tcls = 0;
        m.txv = m.tyv = m.twv = m.thv = m.iou_best = 0.0f;

        if (valid) {
            float gx = t1 * NW, gy = t2 * NH, gw = t3 * NW, gh = t4 * NH;

            float* bx = g_boxes[b][cnt];
            bx[0] = gx - gw * 0.5f; bx[1] = gy - gh * 0.5f;
            bx[2] = gx + gw * 0.5f; bx[3] = gy + gh * 0.5f;
            bx[4] = gw * gh;
            cnt++;

            // best anchor (wh-only IoU), first-max tie-break
            int best = 0; float bestiou = -1.0f;
            for (int a = 0; a < NA; ++a) {
                float aw = anchors[2 * a], ah = anchors[2 * a + 1];
                float inter = fminf(gw, aw) * fminf(gh, ah);
                float uni = gw * gh + aw * ah - inter;
                float io = uni > 0.0f ? inter / uni : 0.0f;
                if (io > bestiou) { bestiou = io; best = a; }
            }
            int gi = min(max((int)gx, 0), NW - 1);
            int gj = min(max((int)gy, 0), NH - 1);
            int flat = ((b * NA + best) * NH + gj) * NW + gi;
            float aw = anchors[2 * best], ah = anchors[2 * best + 1];

            m.flat = flat;
            m.txv = gx - (float)gi;
            m.tyv = gy - (float)gj;
            m.twv = logf(fmaxf(gw, 1e-12f) / aw);
            m.thv = logf(fmaxf(gh, 1e-12f) / ah);
            m.tcls = (int)cls;

            // predicted box at the assigned cell
            int base = ((b * CH + best * (5 + NCLS)) * NH + gj) * NW + gi;
            float o0 = out[base];
            float o1 = out[base + SPLANE];
            float o2 = out[base + 2 * SPLANE];
            float o3 = out[base + 3 * SPLANE];
            float px = sigm(o0) + (float)gi;
            float py = sigm(o1) + (float)gj;
            float pw = expf(o2) * aw;
            float ph = expf(o3) * ah;
            m.iou_best = iou_corners(px - pw * 0.5f, py - ph * 0.5f,
                                     px + pw * 0.5f, py + ph * 0.5f, pw * ph,
                                     gx - gw * 0.5f, gy - gh * 0.5f,
                                     gx + gw * 0.5f, gy + gh * 0.5f, gw * gh);
        }
        g_meta[b][g] = m;
    }
    g_cnt[b] = cnt;
}

// ---------------------------------------------------------------------------
// Pass B: base per-cell loss over all nB*nA*nH*nW cells.
// grid = (CELLS_PER_B/256, NB), block = 256
// ---------------------------------------------------------------------------
__global__ void pass_b(const float* __restrict__ out, const float* __restrict__ anchors) {
    __shared__ float sb[MAXGT * 5];
    __shared__ float sanc[2 * NA];
    __shared__ int scnt;
    __shared__ float ssum[8];

    int b = blockIdx.y;
    int tid = threadIdx.x;
    if (tid == 0) scnt = g_cnt[b];
    if (tid < 2 * NA) sanc[tid] = anchors[tid];
    for (int k = tid; k < MAXGT * 5; k += blockDim.x)
        sb[k] = ((const float*)g_boxes[b])[k];
    __syncthreads();

    int cnt = scnt;
    int cell = blockIdx.x * blockDim.x + tid; // < 20480 exactly

    int a = cell >> 12;
    int rem = cell & 4095;
    int j = rem >> 6;
    int i = rem & 63;
    int base = ((b * CH + a * (5 + NCLS)) * NH + j) * NW + i;

    float o0 = out[base];
    float o1 = out[base + SPLANE];
    float o2 = out[base + 2 * SPLANE];
    float o3 = out[base + 3 * SPLANE];
    float o4 = out[base + 4 * SPLANE];

    float x = sigm(o0), y = sigm(o1), w = o2, h = o3, conf = sigm(o4);
    float aw = sanc[2 * a], ah = sanc[2 * a + 1];

    float px = x + (float)i, py = y + (float)j;
    float pw = expf(w) * aw, ph = expf(h) * ah;
    float px1 = px - pw * 0.5f, py1 = py - ph * 0.5f;
    float px2 = px + pw * 0.5f, py2 = py + ph * 0.5f;
    float parea = pw * ph;

    float cur = 0.0f;
    for (int g = 0; g < cnt; ++g) {
        const float* bx = &sb[g * 5];
        cur = fmaxf(cur, iou_corners(px1, py1, px2, py2, parea,
                                     bx[0], bx[1], bx[2], bx[3], bx[4]));
    }
    float cmb = (cur > SIL_T) ? 0.0f : 1.0f;

    float dx = x - 0.5f, dy = y - 0.5f;
    float local = 0.5f * (dx * dx + dy * dy + w * w + h * h) + 0.5f * cmb * conf * conf;

    // block reduction: warp shuffle then across 8 warps
    for (int off = 16; off > 0; off >>= 1)
        local += __shfl_down_sync(0xffffffffu, local, off);
    if ((tid & 31) == 0) ssum[tid >> 5] = local;
    __syncthreads();
    if (tid < 8) {
        float v = ssum[tid];
        for (int off = 4; off > 0; off >>= 1)
            v += __shfl_down_sync(0xffu, v, off);
        if (tid == 0) atomicAdd(&g_acc, (double)v);
    }
}

// ---------------------------------------------------------------------------
// Pass C: per-GT corrections at assigned cells (+ class NLL).
// grid = NB, block = 64 (first MAXGT threads active)
// ---------------------------------------------------------------------------
__global__ void pass_c(const float* __restrict__ out, const float* __restrict__ anchors) {
    __shared__ float sb[MAXGT * 5];
    int b = blockIdx.x;
    int tid = threadIdx.x;
    int cnt = g_cnt[b];
    for (int k = tid; k < MAXGT * 5; k += blockDim.x)
        sb[k] = ((const float*)g_boxes[b])[k];
    __syncthreads();

    if (tid >= MAXGT) return;
    GtMeta m = g_meta[b][tid];
    if (!m.valid) return;
    // last-write-wins dedup: skip if a later valid GT writes the same cell
    for (int g2 = tid + 1; g2 < MAXGT; ++g2) {
        if (g_meta[b][g2].valid && g_meta[b][g2].flat == m.flat) return;
    }

    int flat = m.flat;
    int i = flat & 63;
    int j = (flat >> 6) & 63;
    int a = (flat >> 12) - b * NA;
    int base = ((b * CH + a * (5 + NCLS)) * NH + j) * NW + i;

    float o0 = out[base];
    float o1 = out[base + SPLANE];
    float o2 = out[base + 2 * SPLANE];
    float o3 = out[base + 3 * SPLANE];
    float o4 = out[base + 4 * SPLANE];
    float x = sigm(o0), y = sigm(o1), w = o2, h = o3, conf = sigm(o4);

    // recompute this cell's base conf_mask (cur_iou vs all GT boxes)
    float aw = anchors[2 * a], ah = anchors[2 * a + 1];
    float px = x + (float)i, py = y + (float)j;
    float pw = expf(w) * aw, ph = expf(h) * ah;
    float px1 = px - pw * 0.5f, py1 = py - ph * 0.5f;
    float px2 = px + pw * 0.5f, py2 = py + ph * 0.5f;
    float parea = pw * ph;
    float cur = 0.0f;
    for (int g = 0; g < cnt; ++g) {
        const float* bx = &sb[g * 5];
        cur = fmaxf(cur, iou_corners(px1, py1, px2, py2, parea,
                                     bx[0], bx[1], bx[2], bx[3], bx[4]));
    }
    float cmb = (cur > SIL_T) ? 0.0f : 1.0f;

    float d = 0.0f, e;
    e = x - m.txv;      d += 0.5f * e * e;
    e = x - 0.5f;       d -= 0.5f * e * e;
    e = y - m.tyv;      d += 0.5f * e * e;
    e = y - 0.5f;       d -= 0.5f * e * e;
    e = w - m.twv;      d += 0.5f * e * e;  d -= 0.5f * w * w;
    e = h - m.thv;      d += 0.5f * e * e;  d -= 0.5f * h * h;
    e = conf - m.iou_best; d += 0.5f * 5.0f * e * e;
    d -= 0.5f * cmb * conf * conf;

    // class NLL: logsumexp over 20 class channels minus the target logit
    float mx = -1e30f;
    for (int c = 0; c < NCLS; ++c)
        mx = fmaxf(mx, out[base + (5 + c) * SPLANE]);
    float s = 0.0f;
    for (int c = 0; c < NCLS; ++c)
        s += expf(out[base + (5 + c) * SPLANE] - mx);
    float lse = mx + logf(s);
    d += lse - out[base + (5 + m.tcls) * SPLANE];

    atomicAdd(&g_acc, (double)d);
}

__global__ void finalize_k(float* o) {
    if (threadIdx.x == 0) o[0] = (float)g_acc;
}

extern "C" void kernel_launch(void* const* d_in, const int* in_sizes, int n_in,
                              void* d_out, int out_size) {
    const float* out = (const float*)d_in[0];
    const float* tgt = (const float*)d_in[1];
    const float* anc = (const float*)d_in[2];

    pass_a<<<1, 32>>>(out, tgt, anc);
    dim3 grid(CELLS_PER_B / 256, NB);
    pass_b<<<grid, 256>>>(out, anc);
    pass_c<<<NB, 64>>>(out, anc);
    finalize_k<<<1, 32>>>((float*)d_out);
}

// round 2
// speedup vs baseline: 2.0751x; 2.0751x over previous
#include <cuda_runtime.h>
#include <math.h>

// Problem constants (fixed by the reference setup_inputs)
#define NB 16
#define NA 5
#define NCLS 20
#define NH 64
#define NW 64
#define MAXGT 50
#define CH (NA * (5 + NCLS))       // 125
#define SPLANE (NH * NW)           // 4096
#define SIL_T 0.6f
#define NCB 80                     // 20480 cells / 256 threads
#define BX (NCB + 1)               // 81 (last column does the GT-correction work)
#define NBLOCKS (BX * NB)          // 1296

__device__ double   g_part[NBLOCKS];
__device__ unsigned g_counter = 0;

__device__ __forceinline__ float sigm(float v) { return 1.0f / (1.0f + expf(-v)); }

__device__ __forceinline__ float iou_corners(float px1, float py1, float px2, float py2, float parea,
                                             float bx1, float by1, float bx2, float by2, float barea) {
    float iw = fmaxf(fminf(px2, bx2) - fmaxf(px1, bx1), 0.0f);
    float ih = fmaxf(fminf(py2, by2) - fmaxf(py1, by1), 0.0f);
    float inter = iw * ih;
    float uni = parea + barea - inter;
    return uni > 0.0f ? inter / uni : 0.0f;
}

__global__ __launch_bounds__(256) void yolo_fused(const float* __restrict__ out,
                                                  const float* __restrict__ tgt,
                                                  const float* __restrict__ anc,
                                                  float* __restrict__ res) {
    __shared__ float sbox[MAXGT * 5];   // compacted valid GT boxes: x1,y1,x2,y2,area
    __shared__ float sg[MAXGT][5];      // gx,gy,gw,gh,cls (raw, uncompacted)
    __shared__ int   sval[MAXGT];
    __shared__ int   scnt;
    __shared__ float sanc[2 * NA];
    __shared__ float ssum[8];
    __shared__ int   sflat[MAXGT];
    __shared__ bool  isLast;
    __shared__ double dsum[8];

    const int b = blockIdx.y;
    const int bx = blockIdx.x;
    const int tid = threadIdx.x;

    // ---- GT preprocessing (redundant per block; trivial cost) ----
    if (tid < 2 * NA) sanc[tid] = anc[tid];
    if (tid < MAXGT) {
        const float* t = tgt + (b * MAXGT + tid) * 5;
        float c = t[0], t1 = t[1], t2 = t[2], t3 = t[3], t4 = t[4];
        sval[tid] = (t1 > 0.0f);
        sg[tid][0] = t1 * NW;
        sg[tid][1] = t2 * NH;
        sg[tid][2] = t3 * NW;
        sg[tid][3] = t4 * NH;
        sg[tid][4] = c;
    }
    __syncthreads();
    if (tid < MAXGT && sval[tid]) {
        int idx = 0;
        for (int g = 0; g < tid; ++g) idx += sval[g];
        float gx = sg[tid][0], gy = sg[tid][1], gw = sg[tid][2], gh = sg[tid][3];
        float* p = &sbox[idx * 5];
        p[0] = gx - gw * 0.5f; p[1] = gy - gh * 0.5f;
        p[2] = gx + gw * 0.5f; p[3] = gy + gh * 0.5f;
        p[4] = gw * gh;
    }
    if (tid == 0) {
        int c = 0;
        for (int g = 0; g < MAXGT; ++g) c += sval[g];
        scnt = c;
    }
    __syncthreads();

    const int cnt = scnt;
    float local = 0.0f;

    if (bx < NCB) {
        // ---- base per-cell loss over 256 cells of this batch ----
        int cell = bx * 256 + tid;           // < 20480
        int a = cell >> 12;
        int rem = cell & 4095;
        int j = rem >> 6;
        int i = rem & 63;
        int base = ((b * CH + a * (5 + NCLS)) * NH + j) * NW + i;

        float o0 = out[base];
        float o1 = out[base + SPLANE];
        float o2 = out[base + 2 * SPLANE];
        float o3 = out[base + 3 * SPLANE];
        float o4 = out[base + 4 * SPLANE];

        float x = sigm(o0), y = sigm(o1), w = o2, h = o3, conf = sigm(o4);
        float aw = sanc[2 * a], ah = sanc[2 * a + 1];

        float px = x + (float)i, py = y + (float)j;
        float pw = expf(w) * aw, ph = expf(h) * ah;
        float px1 = px - pw * 0.5f, py1 = py - ph * 0.5f;
        float px2 = px + pw * 0.5f, py2 = py + ph * 0.5f;
        float parea = pw * ph;

        float cur = 0.0f;
        for (int g = 0; g < cnt; ++g) {
            const float* bxp = &sbox[g * 5];
            cur = fmaxf(cur, iou_corners(px1, py1, px2, py2, parea,
                                         bxp[0], bxp[1], bxp[2], bxp[3], bxp[4]));
        }
        float cmb = (cur > SIL_T) ? 0.0f : 1.0f;

        float dx = x - 0.5f, dy = y - 0.5f;
        local = 0.5f * (dx * dx + dy * dy + w * w + h * h) + 0.5f * cmb * conf * conf;
    } else {
        // ---- per-GT correction terms (one thread per GT slot) ----
        int myvalid = (tid < MAXGT) ? sval[tid] : 0;
        int best = 0;
        float txv = 0.f, tyv = 0.f, twv = 0.f, thv = 0.f;
        int gi = 0, gj = 0, tcls = 0;
        float gx = 0.f, gy = 0.f, gw = 0.f, gh = 0.f;

        if (tid < MAXGT) {
            if (myvalid) {
                gx = sg[tid][0]; gy = sg[tid][1]; gw = sg[tid][2]; gh = sg[tid][3];
                float bestiou = -1.0f;
                for (int a = 0; a < NA; ++a) {
                    float aw = sanc[2 * a], ah = sanc[2 * a + 1];
                    float inter = fminf(gw, aw) * fminf(gh, ah);
                    float uni = gw * gh + aw * ah - inter;
                    float io = uni > 0.0f ? inter / uni : 0.0f;
                    if (io > bestiou) { bestiou = io; best = a; }
                }
                gi = min(max((int)gx, 0), NW - 1);
                gj = min(max((int)gy, 0), NH - 1);
                sflat[tid] = ((b * NA + best) * NH + gj) * NW + gi;
                float aw = sanc[2 * best], ah = sanc[2 * best + 1];
                txv = gx - (float)gi;
                tyv = gy - (float)gj;
                twv = logf(fmaxf(gw, 1e-12f) / aw);
                thv = logf(fmaxf(gh, 1e-12f) / ah);
                tcls = (int)sg[tid][4];
            } else {
                sflat[tid] = -1;
            }
        }
        __syncthreads();

        if (tid < MAXGT && myvalid) {
            // last-write-wins: skip if a later valid GT writes the same cell
            bool skip = false;
            int myflat = sflat[tid];
            for (int g2 = tid + 1; g2 < MAXGT; ++g2)
                if (sflat[g2] == myflat) skip = true;

            if (!skip) {
                int i = myflat & 63;
                int j = (myflat >> 6) & 63;
                int a = best;
                int base = ((b * CH + a * (5 + NCLS)) * NH + j) * NW + i;

                float o0 = out[base];
                float o1 = out[base + SPLANE];
                float o2 = out[base + 2 * SPLANE];
                float o3 = out[base + 3 * SPLANE];
                float o4 = out[base + 4 * SPLANE];
                float x = sigm(o0), y = sigm(o1), w = o2, h = o3, conf = sigm(o4);

                float aw = sanc[2 * a], ah = sanc[2 * a + 1];
                float px = x + (float)i, py = y + (float)j;
                float pw = expf(w) * aw, ph = expf(h) * ah;
                float px1 = px - pw * 0.5f, py1 = py - ph * 0.5f;
                float px2 = px + pw * 0.5f, py2 = py + ph * 0.5f;
                float parea = pw * ph;

                float cur = 0.0f;
                for (int g = 0; g < cnt; ++g) {
                    const float* bxp = &sbox[g * 5];
                    cur = fmaxf(cur, iou_corners(px1, py1, px2, py2, parea,
                                                 bxp[0], bxp[1], bxp[2], bxp[3], bxp[4]));
                }
                float cmb = (cur > SIL_T) ? 0.0f : 1.0f;

                // iou of predicted box at this cell vs THIS gt box
                float iou_best = iou_corners(px1, py1, px2, py2, parea,
                                             gx - gw * 0.5f, gy - gh * 0.5f,
                                             gx + gw * 0.5f, gy + gh * 0.5f, gw * gh);

                float d = 0.0f, e;
                e = x - txv;       d += 0.5f * e * e;
                e = x - 0.5f;      d -= 0.5f * e * e;
                e = y - tyv;       d += 0.5f * e * e;
                e = y - 0.5f;      d -= 0.5f * e * e;
                e = w - twv;       d += 0.5f * e * e;  d -= 0.5f * w * w;
                e = h - thv;       d += 0.5f * e * e;  d -= 0.5f * h * h;
                e = conf - iou_best; d += 0.5f * 5.0f * e * e;
                d -= 0.5f * cmb * conf * conf;

                // class NLL
                float mx = -1e30f;
                for (int c = 0; c < NCLS; ++c)
                    mx = fmaxf(mx, out[base + (5 + c) * SPLANE]);
                float s = 0.0f;
                for (int c = 0; c < NCLS; ++c)
                    s += expf(out[base + (5 + c) * SPLANE] - mx);
                d += mx + logf(s) - out[base + (5 + tcls) * SPLANE];

                local = d;
            }
        }
    }

    // ---- block reduction (float) -> one double partial per block ----
    for (int off = 16; off > 0; off >>= 1)
        local += __shfl_down_sync(0xffffffffu, local, off);
    if ((tid & 31) == 0) ssum[tid >> 5] = local;
    __syncthreads();
    if (tid < 8) {
        float v = ssum[tid];
        for (int off = 4; off > 0; off >>= 1)
            v += __shfl_down_sync(0xffu, v, off);
        if (tid == 0) g_part[b * BX + bx] = (double)v;
    }

    // ---- last-block-done final reduction (single-launch, replay-safe) ----
    if (tid == 0) {
        __threadfence();
        unsigned v = atomicAdd(&g_counter, 1u);
        isLast = (v == NBLOCKS - 1);
    }
    __syncthreads();
    if (isLast) {
        __threadfence();
        double s = 0.0;
        for (int k = tid; k < NBLOCKS; k += 256)
            s += __ldcg(&g_part[k]);
        for (int off = 16; off > 0; off >>= 1)
            s += __shfl_down_sync(0xffffffffu, s, off);
        if ((tid & 31) == 0) dsum[tid >> 5] = s;
        __syncthreads();
        if (tid < 8) {
            double v2 = dsum[tid];
            for (int off = 4; off > 0; off >>= 1)
                v2 += __shfl_down_sync(0xffu, v2, off);
            if (tid == 0) {
                res[0] = (float)v2;
                g_counter = 0;   // reset for next graph replay
            }
        }
    }
}

extern "C" void kernel_launch(void* const* d_in, const int* in_sizes, int n_in,
                              void* d_out, int out_size) {
    const float* out = (const float*)d_in[0];
    const float* tgt = (const float*)d_in[1];
    const float* anc = (const float*)d_in[2];

    dim3 grid(BX, NB);
    yolo_fused<<<grid, 256>>>(out, tgt, anc, (float*)d_out);
}

// round 3
// speedup vs baseline: 2.7383x; 1.3196x over previous
#include <cuda_runtime.h>
#include <math.h>

// Problem constants (fixed by the reference setup_inputs)
#define NB 16
#define NA 5
#define NCLS 20
#define NH 64
#define NW 64
#define MAXGT 50
#define CH (NA * (5 + NCLS))       // 125
#define SPLANE (NH * NW)           // 4096
#define SIL_T 0.6f
#define NCB 80                     // 20480 cells / 256 threads
#define BX (NCB + 1)               // 81 (last column does the GT-correction work)
#define NBLOCKS (BX * NB)          // 1296

__device__ double   g_part[NBLOCKS];
__device__ unsigned g_counter = 0;

__device__ __forceinline__ float sigm_fast(float v) {
    return __fdividef(1.0f, 1.0f + __expf(-v));
}
__device__ __forceinline__ float sigm(float v) { return 1.0f / (1.0f + expf(-v)); }

__device__ __forceinline__ float iou_corners(float px1, float py1, float px2, float py2, float parea,
                                             float bx1, float by1, float bx2, float by2, float barea) {
    float iw = fmaxf(fminf(px2, bx2) - fmaxf(px1, bx1), 0.0f);
    float ih = fmaxf(fminf(py2, by2) - fmaxf(py1, by1), 0.0f);
    float inter = iw * ih;
    float uni = parea + barea - inter;
    return uni > 0.0f ? inter / uni : 0.0f;
}

__global__ __launch_bounds__(256) void yolo_fused(const float* __restrict__ out,
                                                  const float* __restrict__ tgt,
                                                  const float* __restrict__ anc,
                                                  float* __restrict__ res) {
    // compacted valid GT boxes: x1,y1,x2,y2, 0.6*area
    __shared__ float sbox[MAXGT * 5];
    __shared__ float sg[MAXGT][5];      // gx,gy,gw,gh,cls (raw, uncompacted)
    __shared__ int   sval[MAXGT];
    __shared__ int   scnt;
    __shared__ float sanc[2 * NA];
    __shared__ float ssum[8];
    __shared__ int   sflat[MAXGT];
    __shared__ bool  isLast;
    __shared__ double dsum[8];

    const int b = blockIdx.y;
    const int bx = blockIdx.x;
    const int tid = threadIdx.x;

    // ---- GT preprocessing (redundant per block; trivial cost) ----
    if (tid < 2 * NA) sanc[tid] = anc[tid];
    if (tid < MAXGT) {
        const float* t = tgt + (b * MAXGT + tid) * 5;
        float c = t[0], t1 = t[1], t2 = t[2], t3 = t[3], t4 = t[4];
        sval[tid] = (t1 > 0.0f);
        sg[tid][0] = t1 * NW;
        sg[tid][1] = t2 * NH;
        sg[tid][2] = t3 * NW;
        sg[tid][3] = t4 * NH;
        sg[tid][4] = c;
    }
    __syncthreads();
    if (tid < MAXGT && sval[tid]) {
        int idx = 0;
        for (int g = 0; g < tid; ++g) idx += sval[g];
        float gx = sg[tid][0], gy = sg[tid][1], gw = sg[tid][2], gh = sg[tid][3];
        float* p = &sbox[idx * 5];
        p[0] = gx - gw * 0.5f; p[1] = gy - gh * 0.5f;
        p[2] = gx + gw * 0.5f; p[3] = gy + gh * 0.5f;
        p[4] = SIL_T * (gw * gh);          // pre-scaled by threshold
    }
    if (tid == 0) {
        int c = 0;
        for (int g = 0; g < MAXGT; ++g) c += sval[g];
        scnt = c;
    }
    __syncthreads();

    const int cnt = scnt;
    float local = 0.0f;

    if (bx < NCB) {
        // ---- base per-cell loss over 256 cells of this batch ----
        int cell = bx * 256 + tid;           // < 20480
        int a = cell >> 12;
        int rem = cell & 4095;
        int j = rem >> 6;
        int i = rem & 63;
        int base = ((b * CH + a * (5 + NCLS)) * NH + j) * NW + i;

        float o0 = out[base];
        float o1 = out[base + SPLANE];
        float o2 = out[base + 2 * SPLANE];
        float o3 = out[base + 3 * SPLANE];
        float o4 = out[base + 4 * SPLANE];

        float x = sigm_fast(o0), y = sigm_fast(o1), w = o2, h = o3, conf = sigm_fast(o4);
        float aw = sanc[2 * a], ah = sanc[2 * a + 1];

        float px = x + (float)i, py = y + (float)j;
        float pw = __expf(w) * aw, ph = __expf(h) * ah;
        float px1 = px - pw * 0.5f, py1 = py - ph * 0.5f;
        float px2 = px + pw * 0.5f, py2 = py + ph * 0.5f;
        float p6 = SIL_T * (pw * ph);       // 0.6 * parea

        // predicate: exists g with IoU > 0.6  <=>  1.6*inter > 0.6*(parea+barea)
        bool over = false;
        #pragma unroll 2
        for (int g = 0; g < cnt; ++g) {
            const float* bxp = &sbox[g * 5];
            float iw = fminf(px2, bxp[2]) - fmaxf(px1, bxp[0]);
            float ih = fminf(py2, bxp[3]) - fmaxf(py1, bxp[1]);
            iw = fmaxf(iw, 0.0f);
            ih = fmaxf(ih, 0.0f);
            float inter = iw * ih;
            over |= (1.0f + SIL_T) * inter > (p6 + bxp[4]);
        }
        float cmb = over ? 0.0f : 1.0f;

        float dx = x - 0.5f, dy = y - 0.5f;
        local = 0.5f * (dx * dx + dy * dy + w * w + h * h) + 0.5f * cmb * conf * conf;
    } else {
        // ---- per-GT correction terms (one thread per GT slot) ----
        int myvalid = (tid < MAXGT) ? sval[tid] : 0;
        int best = 0;
        float txv = 0.f, tyv = 0.f, twv = 0.f, thv = 0.f;
        int tcls = 0;
        float gx = 0.f, gy = 0.f, gw = 0.f, gh = 0.f;

        if (tid < MAXGT) {
            if (myvalid) {
                gx = sg[tid][0]; gy = sg[tid][1]; gw = sg[tid][2]; gh = sg[tid][3];
                float bestiou = -1.0f;
                for (int a = 0; a < NA; ++a) {
                    float aw = sanc[2 * a], ah = sanc[2 * a + 1];
                    float inter = fminf(gw, aw) * fminf(gh, ah);
                    float uni = gw * gh + aw * ah - inter;
                    float io = uni > 0.0f ? inter / uni : 0.0f;
                    if (io > bestiou) { bestiou = io; best = a; }
                }
                int gi = min(max((int)gx, 0), NW - 1);
                int gj = min(max((int)gy, 0), NH - 1);
                sflat[tid] = ((b * NA + best) * NH + gj) * NW + gi;
                float aw = sanc[2 * best], ah = sanc[2 * best + 1];
                txv = gx - (float)gi;
                tyv = gy - (float)gj;
                twv = logf(fmaxf(gw, 1e-12f) / aw);
                thv = logf(fmaxf(gh, 1e-12f) / ah);
                tcls = (int)sg[tid][4];
            } else {
                sflat[tid] = -1;
            }
        }
        __syncthreads();

        if (tid < MAXGT && myvalid) {
            // last-write-wins: skip if a later valid GT writes the same cell
            bool skip = false;
            int myflat = sflat[tid];
            for (int g2 = tid + 1; g2 < MAXGT; ++g2)
                if (sflat[g2] == myflat) skip = true;

            if (!skip) {
                int i = myflat & 63;
                int j = (myflat >> 6) & 63;
                int a = best;
                int base = ((b * CH + a * (5 + NCLS)) * NH + j) * NW + i;

                float o0 = out[base];
                float o1 = out[base + SPLANE];
                float o2 = out[base + 2 * SPLANE];
                float o3 = out[base + 3 * SPLANE];
                float o4 = out[base + 4 * SPLANE];
                float x = sigm(o0), y = sigm(o1), w = o2, h = o3, conf = sigm(o4);

                float aw = sanc[2 * a], ah = sanc[2 * a + 1];
                float px = x + (float)i, py = y + (float)j;
                float pw = expf(w) * aw, ph = expf(h) * ah;
                float px1 = px - pw * 0.5f, py1 = py - ph * 0.5f;
                float px2 = px + pw * 0.5f, py2 = py + ph * 0.5f;
                float parea = pw * ph;
                float p6 = SIL_T * parea;

                bool over = false;
                for (int g = 0; g < cnt; ++g) {
                    const float* bxp = &sbox[g * 5];
                    float iw = fmaxf(fminf(px2, bxp[2]) - fmaxf(px1, bxp[0]), 0.0f);
                    float ih = fmaxf(fminf(py2, bxp[3]) - fmaxf(py1, bxp[1]), 0.0f);
                    float inter = iw * ih;
                    over |= (1.0f + SIL_T) * inter > (p6 + bxp[4]);
                }
                float cmb = over ? 0.0f : 1.0f;

                // iou of predicted box at this cell vs THIS gt box (precise)
                float iou_best = iou_corners(px1, py1, px2, py2, parea,
                                             gx - gw * 0.5f, gy - gh * 0.5f,
                                             gx + gw * 0.5f, gy + gh * 0.5f, gw * gh);

                float d = 0.0f, e;
                e = x - txv;       d += 0.5f * e * e;
                e = x - 0.5f;      d -= 0.5f * e * e;
                e = y - tyv;       d += 0.5f * e * e;
                e = y - 0.5f;      d -= 0.5f * e * e;
                e = w - twv;       d += 0.5f * e * e;  d -= 0.5f * w * w;
                e = h - thv;       d += 0.5f * e * e;  d -= 0.5f * h * h;
                e = conf - iou_best; d += 0.5f * 5.0f * e * e;
                d -= 0.5f * cmb * conf * conf;

                // class NLL
                float mx = -1e30f;
                for (int c = 0; c < NCLS; ++c)
                    mx = fmaxf(mx, out[base + (5 + c) * SPLANE]);
                float s = 0.0f;
                for (int c = 0; c < NCLS; ++c)
                    s += expf(out[base + (5 + c) * SPLANE] - mx);
                d += mx + logf(s) - out[base + (5 + tcls) * SPLANE];

                local = d;
            }
        }
    }

    // ---- block reduction (float) -> one double partial per block ----
    for (int off = 16; off > 0; off >>= 1)
        local += __shfl_down_sync(0xffffffffu, local, off);
    if ((tid & 31) == 0) ssum[tid >> 5] = local;
    __syncthreads();
    if (tid < 8) {
        float v = ssum[tid];
        for (int off = 4; off > 0; off >>= 1)
            v += __shfl_down_sync(0xffu, v, off);
        if (tid == 0) g_part[b * BX + bx] = (double)v;
    }

    // ---- last-block-done final reduction (single-launch, replay-safe) ----
    if (tid == 0) {
        __threadfence();
        unsigned v = atomicAdd(&g_counter, 1u);
        isLast = (v == NBLOCKS - 1);
    }
    __syncthreads();
    if (isLast) {
        __threadfence();
        double s = 0.0;
        for (int k = tid; k < NBLOCKS; k += 256)
            s += __ldcg(&g_part[k]);
        for (int off = 16; off > 0; off >>= 1)
            s += __shfl_down_sync(0xffffffffu, s, off);
        if ((tid & 31) == 0) dsum[tid >> 5] = s;
        __syncthreads();
        if (tid < 8) {
            double v2 = dsum[tid];
            for (int off = 4; off > 0; off >>= 1)
                v2 += __shfl_down_sync(0xffu, v2, off);
            if (tid == 0) {
                res[0] = (float)v2;
                g_counter = 0;   // reset for next graph replay
            }
        }
    }
}

extern "C" void kernel_launch(void* const* d_in, const int* in_sizes, int n_in,
                              void* d_out, int out_size) {
    const float* out = (const float*)d_in[0];
    const float* tgt = (const float*)d_in[1];
    const float* anc = (const float*)d_in[2];

    dim3 grid(BX, NB);
    yolo_fused<<<grid, 256>>>(out, tgt, anc, (float*)d_out);
}

// round 5
// speedup vs baseline: 3.5995x; 1.3145x over previous
#include <cuda_runtime.h>
#include <math.h>

// Problem constants (fixed by the reference setup_inputs)
#define NB 16
#define NA 5
#define NCLS 20
#define NH 64
#define NW 64
#define MAXGT 50
#define CH (NA * (5 + NCLS))       // 125
#define SPLANE (NH * NW)           // 4096
#define SIL_T 0.6f
#define NCB 20                     // 20480 cells / (256 threads * 4 cells)
#define BX (NCB + 1)               // 21 (last column: GT-correction work)
#define NBLOCKS (BX * NB)          // 336

__device__ double   g_part[NBLOCKS];
__device__ unsigned g_counter = 0;

__device__ __forceinline__ float sigm_fast(float v) {
    return __fdividef(1.0f, 1.0f + __expf(-v));
}
__device__ __forceinline__ float sigm(float v) { return 1.0f / (1.0f + expf(-v)); }

__device__ __forceinline__ float iou_corners(float px1, float py1, float px2, float py2, float parea,
                                             float bx1, float by1, float bx2, float by2, float barea) {
    float iw = fmaxf(fminf(px2, bx2) - fmaxf(px1, bx1), 0.0f);
    float ih = fmaxf(fminf(py2, by2) - fmaxf(py1, by1), 0.0f);
    float inter = iw * ih;
    float uni = parea + barea - inter;
    return uni > 0.0f ? inter / uni : 0.0f;
}

__global__ __launch_bounds__(256) void yolo_fused(const float* __restrict__ out,
                                                  const float* __restrict__ tgt,
                                                  const float* __restrict__ anc,
                                                  float* __restrict__ res) {
    __shared__ float straw[MAXGT * 5];  // raw target rows (cls, tx, ty, tw, th)
    __shared__ float sbox[MAXGT * 5];   // compacted: x1,y1,x2,y2, 0.6*area
    __shared__ float sanc[2 * NA];
    __shared__ int   swcnt[2];
    __shared__ float ssum[8];
    __shared__ int   sflat[MAXGT];
    __shared__ bool  isLast;
    __shared__ double dsum[8];

    const int b = blockIdx.y;
    const int bx = blockIdx.x;
    const int tid = threadIdx.x;
    const int lane = tid & 31;
    const int wid = tid >> 5;

    // ---- GT preprocessing: coalesced load + ballot compaction ----
    if (tid < MAXGT * 5) straw[tid] = tgt[b * MAXGT * 5 + tid];
    if (tid < 2 * NA) sanc[tid] = anc[tid];
    __syncthreads();

    bool valid = false;
    float gx = 0.f, gy = 0.f, gw = 0.f, gh = 0.f;
    if (tid < MAXGT) {
        float t1 = straw[tid * 5 + 1];
        valid = (t1 > 0.0f);
        gx = t1 * NW;
        gy = straw[tid * 5 + 2] * NH;
        gw = straw[tid * 5 + 3] * NW;
        gh = straw[tid * 5 + 4] * NH;
    }
    unsigned m = __ballot_sync(0xffffffffu, valid);
    if (wid < 2 && lane == 0) swcnt[wid] = __popc(m);
    __syncthreads();
    const int cnt = swcnt[0] + swcnt[1];
    if (valid) {
        int idx = __popc(m & ((1u << lane) - 1u)) + (wid == 1 ? swcnt[0] : 0);
        float* p = &sbox[idx * 5];
        p[0] = gx - gw * 0.5f; p[1] = gy - gh * 0.5f;
        p[2] = gx + gw * 0.5f; p[3] = gy + gh * 0.5f;
        p[4] = SIL_T * (gw * gh);
    }
    __syncthreads();

    float local = 0.0f;

    if (bx < NCB) {
        // ---- base loss: 4 consecutive cells per thread (float4 loads) ----
        int cell4 = bx * 256 + tid;      // 0..5119 (units of 4 cells)
        int a = cell4 >> 10;             // 1024 groups per anchor plane
        int rem = cell4 & 1023;
        int j = rem >> 4;
        int i0 = (rem & 15) * 4;
        int base = ((b * CH + a * (5 + NCLS)) * NH + j) * NW + i0;

        float4 o0 = *(const float4*)(out + base);
        float4 o1 = *(const float4*)(out + base + SPLANE);
        float4 o2 = *(const float4*)(out + base + 2 * SPLANE);
        float4 o3 = *(const float4*)(out + base + 3 * SPLANE);
        float4 o4 = *(const float4*)(out + base + 4 * SPLANE);

        const float aw = sanc[2 * a], ah = sanc[2 * a + 1];
        const float fj = (float)j;

        float xs[4] = {sigm_fast(o0.x), sigm_fast(o0.y), sigm_fast(o0.z), sigm_fast(o0.w)};
        float ys[4] = {sigm_fast(o1.x), sigm_fast(o1.y), sigm_fast(o1.z), sigm_fast(o1.w)};
        float ws[4] = {o2.x, o2.y, o2.z, o2.w};
        float hs[4] = {o3.x, o3.y, o3.z, o3.w};
        float cs[4] = {sigm_fast(o4.x), sigm_fast(o4.y), sigm_fast(o4.z), sigm_fast(o4.w)};

        float px1[4], py1[4], px2[4], py2[4], p6[4];
        bool  over[4];
        #pragma unroll
        for (int c = 0; c < 4; ++c) {
            float px = xs[c] + (float)(i0 + c);
            float py = ys[c] + fj;
            float pw = __expf(ws[c]) * aw;
            float ph = __expf(hs[c]) * ah;
            px1[c] = px - pw * 0.5f; py1[c] = py - ph * 0.5f;
            px2[c] = px + pw * 0.5f; py2[c] = py + ph * 0.5f;
            p6[c]  = SIL_T * (pw * ph);
            over[c] = false;
        }

        for (int g = 0; g < cnt; ++g) {
            const float bx1 = sbox[g * 5 + 0];
            const float by1 = sbox[g * 5 + 1];
            const float bx2 = sbox[g * 5 + 2];
            const float by2 = sbox[g * 5 + 3];
            const float b6  = sbox[g * 5 + 4];
            #pragma unroll
            for (int c = 0; c < 4; ++c) {
                float iw = fmaxf(fminf(px2[c], bx2) - fmaxf(px1[c], bx1), 0.0f);
                float ih = fmaxf(fminf(py2[c], by2) - fmaxf(py1[c], by1), 0.0f);
                float inter = iw * ih;
                over[c] |= (1.0f + SIL_T) * inter > (p6[c] + b6);
            }
        }

        #pragma unroll
        for (int c = 0; c < 4; ++c) {
            float dx = xs[c] - 0.5f, dy = ys[c] - 0.5f;
            float cmb = over[c] ? 0.0f : 1.0f;
            local += 0.5f * (dx * dx + dy * dy + ws[c] * ws[c] + hs[c] * hs[c])
                   + 0.5f * cmb * cs[c] * cs[c];
        }
    } else {
        // ---- per-GT correction terms (one thread per GT slot) ----
        int best = 0;
        float txv = 0.f, tyv = 0.f, twv = 0.f, thv = 0.f;
        int tcls = 0;

        if (tid < MAXGT) {
            if (valid) {
                float bestiou = -1.0f;
                for (int a = 0; a < NA; ++a) {
                    float aw = sanc[2 * a], ah = sanc[2 * a + 1];
                    float inter = fminf(gw, aw) * fminf(gh, ah);
                    float uni = gw * gh + aw * ah - inter;
                    float io = uni > 0.0f ? inter / uni : 0.0f;
                    if (io > bestiou) { bestiou = io; best = a; }
                }
                int gi = min(max((int)gx, 0), NW - 1);
                int gj = min(max((int)gy, 0), NH - 1);
                sflat[tid] = ((b * NA + best) * NH + gj) * NW + gi;
                float aw = sanc[2 * best], ah = sanc[2 * best + 1];
                txv = gx - (float)gi;
                tyv = gy - (float)gj;
                twv = logf(fmaxf(gw, 1e-12f) / aw);
                thv = logf(fmaxf(gh, 1e-12f) / ah);
                tcls = (int)straw[tid * 5];
            } else {
                sflat[tid] = -1;
            }
        }
        __syncthreads();

        if (tid < MAXGT && valid) {
            // last-write-wins: skip if a later valid GT writes the same cell
            bool skip = false;
            int myflat = sflat[tid];
            for (int g2 = tid + 1; g2 < MAXGT; ++g2)
                if (sflat[g2] == myflat) skip = true;

            if (!skip) {
                int i = myflat & 63;
                int j = (myflat >> 6) & 63;
                int a = best;
                int base = ((b * CH + a * (5 + NCLS)) * NH + j) * NW + i;

                float o0 = out[base];
                float o1 = out[base + SPLANE];
                float o2 = out[base + 2 * SPLANE];
                float o3 = out[base + 3 * SPLANE];
                float o4 = out[base + 4 * SPLANE];
                float x = sigm(o0), y = sigm(o1), w = o2, h = o3, conf = sigm(o4);

                float aw = sanc[2 * a], ah = sanc[2 * a + 1];
                float px = x + (float)i, py = y + (float)j;
                float pw = expf(w) * aw, ph = expf(h) * ah;
                float px1 = px - pw * 0.5f, py1 = py - ph * 0.5f;
                float px2 = px + pw * 0.5f, py2 = py + ph * 0.5f;
                float parea = pw * ph;
                float p6 = SIL_T * parea;

                bool over = false;
                for (int g = 0; g < cnt; ++g) {
                    const float* bxp = &sbox[g * 5];
                    float iw = fmaxf(fminf(px2, bxp[2]) - fmaxf(px1, bxp[0]), 0.0f);
                    float ih = fmaxf(fminf(py2, bxp[3]) - fmaxf(py1, bxp[1]), 0.0f);
                    float inter = iw * ih;
                    over |= (1.0f + SIL_T) * inter > (p6 + bxp[4]);
                }
                float cmb = over ? 0.0f : 1.0f;

                // iou of predicted box at this cell vs THIS gt box (precise)
                float iou_best = iou_corners(px1, py1, px2, py2, parea,
                                             gx - gw * 0.5f, gy - gh * 0.5f,
                                             gx + gw * 0.5f, gy + gh * 0.5f, gw * gh);

                float d = 0.0f, e;
                e = x - txv;       d += 0.5f * e * e;
                e = x - 0.5f;      d -= 0.5f * e * e;
                e = y - tyv;       d += 0.5f * e * e;
                e = y - 0.5f;      d -= 0.5f * e * e;
                e = w - twv;       d += 0.5f * e * e;  d -= 0.5f * w * w;
                e = h - thv;       d += 0.5f * e * e;  d -= 0.5f * h * h;
                e = conf - iou_best; d += 0.5f * 5.0f * e * e;
                d -= 0.5f * cmb * conf * conf;

                // class NLL
                float mx = -1e30f;
                for (int c = 0; c < NCLS; ++c)
                    mx = fmaxf(mx, out[base + (5 + c) * SPLANE]);
                float s = 0.0f;
                for (int c = 0; c < NCLS; ++c)
                    s += expf(out[base + (5 + c) * SPLANE] - mx);
                d += mx + logf(s) - out[base + (5 + tcls) * SPLANE];

                local = d;
            }
        }
    }

    // ---- block reduction (float) -> one double partial per block ----
    for (int off = 16; off > 0; off >>= 1)
        local += __shfl_down_sync(0xffffffffu, local, off);
    if (lane == 0) ssum[wid] = local;
    __syncthreads();
    if (tid < 8) {
        float v = ssum[tid];
        for (int off = 4; off > 0; off >>= 1)
            v += __shfl_down_sync(0xffu, v, off);
        if (tid == 0) g_part[b * BX + bx] = (double)v;
    }

    // ---- last-block-done final reduction (single-launch, replay-safe) ----
    if (tid == 0) {
        __threadfence();
        unsigned v = atomicAdd(&g_counter, 1u);
        isLast = (v == NBLOCKS - 1);
    }
    __syncthreads();
    if (isLast) {
        __threadfence();
        double s = 0.0;
        for (int k = tid; k < NBLOCKS; k += 256)
            s += __ldcg(&g_part[k]);
        for (int off = 16; off > 0; off >>= 1)
            s += __shfl_down_sync(0xffffffffu, s, off);
        if (lane == 0) dsum[wid] = s;
        __syncthreads();
        if (tid < 8) {
            double v2 = dsum[tid];
            for (int off = 4; off > 0; off >>= 1)
                v2 += __shfl_down_sync(0xffu, v2, off);
            if (tid == 0) {
                res[0] = (float)v2;
                g_counter = 0;   // reset for next graph replay
            }
        }
    }
}

extern "C" void kernel_launch(void* const* d_in, const int* in_sizes, int n_in,
                              void* d_out, int out_size) {
    const float* out = (const float*)d_in[0];
    const float* tgt = (const float*)d_in[1];
    const float* anc = (const float*)d_in[2];

    dim3 grid(BX, NB);
    yolo_fused<<<grid, 256>>>(out, tgt, anc, (float*)d_out);
}

// round 6
// speedup vs baseline: 3.7372x; 1.0383x over previous
#include <cuda_runtime.h>
#include <math.h>

// Problem constants (fixed by the reference setup_inputs)
#define NB 16
#define NA 5
#define NCLS 20
#define NH 64
#define NW 64
#define MAXGT 50
#define CH (NA * (5 + NCLS))       // 125
#define SPLANE (NH * NW)           // 4096
#define SIL_T 0.6f
#define NCB 10                     // 20480 cells / (256 threads * 8 cells)
#define BX (NCB + 1)               // 11 (last column: GT-correction work)
#define NBLOCKS (BX * NB)          // 176

__device__ double   g_part[NBLOCKS];
__device__ unsigned g_counter = 0;

__device__ __forceinline__ float tanh_fast(float v) {
    float r;
    asm("tanh.approx.f32 %0, %1;" : "=f"(r) : "f"(v));
    return r;
}
// sigmoid(v) = 0.5*tanh(v/2) + 0.5   (1 MUFU + 2 FMA)
__device__ __forceinline__ float sigm_fast(float v) {
    return fmaf(0.5f, tanh_fast(0.5f * v), 0.5f);
}
__device__ __forceinline__ float sigm(float v) { return 1.0f / (1.0f + expf(-v)); }

__device__ __forceinline__ float iou_corners(float px1, float py1, float px2, float py2, float parea,
                                             float bx1, float by1, float bx2, float by2, float barea) {
    float iw = fmaxf(fminf(px2, bx2) - fmaxf(px1, bx1), 0.0f);
    float ih = fmaxf(fminf(py2, by2) - fmaxf(py1, by1), 0.0f);
    float inter = iw * ih;
    float uni = parea + barea - inter;
    return uni > 0.0f ? inter / uni : 0.0f;
}

__global__ __launch_bounds__(256) void yolo_fused(const float* __restrict__ out,
                                                  const float* __restrict__ tgt,
                                                  const float* __restrict__ anc,
                                                  float* __restrict__ res) {
    __shared__ float straw[MAXGT * 5];  // raw target rows (cls, tx, ty, tw, th)
    __shared__ float sbox[MAXGT * 5];   // compacted: x1,y1,x2,y2, 0.6*area
    __shared__ float sanc[2 * NA];
    __shared__ int   swcnt[2];
    __shared__ float ssum[8];
    __shared__ int   sflat[MAXGT];
    __shared__ bool  isLast;
    __shared__ double dsum[8];

    const int b = blockIdx.y;
    const int bx = blockIdx.x;
    const int tid = threadIdx.x;
    const int lane = tid & 31;
    const int wid = tid >> 5;

    // ================= prefetch main-plane loads (independent of tgt) =====
    // 8 consecutive cells per thread: unit = bx*256+tid, 512 units per anchor
    // plane -> a = unit>>9, j = (unit&511)>>3, i0 = (unit&7)*8
    float4 o0a, o0b, o1a, o1b, o2a, o2b, o3a, o3b, o4a, o4b;
    int a_ = 0, j_ = 0, i0_ = 0;
    if (bx < NCB) {
        int unit = bx * 256 + tid;
        a_ = unit >> 9;
        int rem = unit & 511;
        j_ = rem >> 3;
        i0_ = (rem & 7) * 8;
        int base = ((b * CH + a_ * (5 + NCLS)) * NH + j_) * NW + i0_;
        o0a = *(const float4*)(out + base);
        o0b = *(const float4*)(out + base + 4);
        o1a = *(const float4*)(out + base + SPLANE);
        o1b = *(const float4*)(out + base + SPLANE + 4);
        o2a = *(const float4*)(out + base + 2 * SPLANE);
        o2b = *(const float4*)(out + base + 2 * SPLANE + 4);
        o3a = *(const float4*)(out + base + 3 * SPLANE);
        o3b = *(const float4*)(out + base + 3 * SPLANE + 4);
        o4a = *(const float4*)(out + base + 4 * SPLANE);
        o4b = *(const float4*)(out + base + 4 * SPLANE + 4);
    }

    // ---- GT preprocessing: coalesced load + ballot compaction ----
    if (tid < MAXGT * 5) straw[tid] = tgt[b * MAXGT * 5 + tid];
    if (tid < 2 * NA) sanc[tid] = anc[tid];
    __syncthreads();

    bool valid = false;
    float gx = 0.f, gy = 0.f, gw = 0.f, gh = 0.f;
    if (tid < MAXGT) {
        float t1 = straw[tid * 5 + 1];
        valid = (t1 > 0.0f);
        gx = t1 * NW;
        gy = straw[tid * 5 + 2] * NH;
        gw = straw[tid * 5 + 3] * NW;
        gh = straw[tid * 5 + 4] * NH;
    }
    unsigned m = __ballot_sync(0xffffffffu, valid);
    if (wid < 2 && lane == 0) swcnt[wid] = __popc(m);
    __syncthreads();
    const int cnt = swcnt[0] + swcnt[1];
    if (valid) {
        int idx = __popc(m & ((1u << lane) - 1u)) + (wid == 1 ? swcnt[0] : 0);
        float* p = &sbox[idx * 5];
        p[0] = gx - gw * 0.5f; p[1] = gy - gh * 0.5f;
        p[2] = gx + gw * 0.5f; p[3] = gy + gh * 0.5f;
        p[4] = SIL_T * (gw * gh);
    }
    __syncthreads();

    float local = 0.0f;

    if (bx < NCB) {
        const float aw = sanc[2 * a_], ah = sanc[2 * a_ + 1];
        const float fj = (float)j_;

        float xs[8] = {sigm_fast(o0a.x), sigm_fast(o0a.y), sigm_fast(o0a.z), sigm_fast(o0a.w),
                       sigm_fast(o0b.x), sigm_fast(o0b.y), sigm_fast(o0b.z), sigm_fast(o0b.w)};
        float ys[8] = {sigm_fast(o1a.x), sigm_fast(o1a.y), sigm_fast(o1a.z), sigm_fast(o1a.w),
                       sigm_fast(o1b.x), sigm_fast(o1b.y), sigm_fast(o1b.z), sigm_fast(o1b.w)};
        float ws[8] = {o2a.x, o2a.y, o2a.z, o2a.w, o2b.x, o2b.y, o2b.z, o2b.w};
        float hs[8] = {o3a.x, o3a.y, o3a.z, o3a.w, o3b.x, o3b.y, o3b.z, o3b.w};
        float cs[8] = {sigm_fast(o4a.x), sigm_fast(o4a.y), sigm_fast(o4a.z), sigm_fast(o4a.w),
                       sigm_fast(o4b.x), sigm_fast(o4b.y), sigm_fast(o4b.z), sigm_fast(o4b.w)};

        float px1[8], py1[8], px2[8], py2[8], p6[8], mi[8];
        #pragma unroll
        for (int c = 0; c < 8; ++c) {
            float px = xs[c] + (float)(i0_ + c);
            float py = ys[c] + fj;
            float pw = __expf(ws[c]) * aw;
            float ph = __expf(hs[c]) * ah;
            px1[c] = px - pw * 0.5f; py1[c] = py - ph * 0.5f;
            px2[c] = px + pw * 0.5f; py2[c] = py + ph * 0.5f;
            p6[c]  = SIL_T * (pw * ph);
            mi[c]  = -1e30f;          // running max of 1.6*inter - 0.6*barea
        }

        for (int g = 0; g < cnt; ++g) {
            const float bx1 = sbox[g * 5 + 0];
            const float by1 = sbox[g * 5 + 1];
            const float bx2 = sbox[g * 5 + 2];
            const float by2 = sbox[g * 5 + 3];
            const float b6  = sbox[g * 5 + 4];
            #pragma unroll
            for (int c = 0; c < 8; ++c) {
                float iw = fmaxf(fminf(px2[c], bx2) - fmaxf(px1[c], bx1), 0.0f);
                float ih = fmaxf(fminf(py2[c], by2) - fmaxf(py1[c], by1), 0.0f);
                // max_iou > 0.6  <=>  max over g of (1.6*inter - 0.6*barea) > 0.6*parea
                mi[c] = fmaxf(mi[c], fmaf((1.0f + SIL_T), iw * ih, -b6));
            }
        }

        #pragma unroll
        for (int c = 0; c < 8; ++c) {
            float dx = xs[c] - 0.5f, dy = ys[c] - 0.5f;
            float cmb = (mi[c] > p6[c]) ? 0.0f : 1.0f;
            local += 0.5f * (dx * dx + dy * dy + ws[c] * ws[c] + hs[c] * hs[c])
                   + 0.5f * cmb * cs[c] * cs[c];
        }
    } else {
        // ---- per-GT correction terms (one thread per GT slot) ----
        int best = 0;
        float txv = 0.f, tyv = 0.f, twv = 0.f, thv = 0.f;
        int tcls = 0;

        if (tid < MAXGT) {
            if (valid) {
                float bestiou = -1.0f;
                for (int a = 0; a < NA; ++a) {
                    float aw = sanc[2 * a], ah = sanc[2 * a + 1];
                    float inter = fminf(gw, aw) * fminf(gh, ah);
                    float uni = gw * gh + aw * ah - inter;
                    float io = uni > 0.0f ? inter / uni : 0.0f;
                    if (io > bestiou) { bestiou = io; best = a; }
                }
                int gi = min(max((int)gx, 0), NW - 1);
                int gj = min(max((int)gy, 0), NH - 1);
                sflat[tid] = ((b * NA + best) * NH + gj) * NW + gi;
                float aw = sanc[2 * best], ah = sanc[2 * best + 1];
                txv = gx - (float)gi;
                tyv = gy - (float)gj;
                twv = logf(fmaxf(gw, 1e-12f) / aw);
                thv = logf(fmaxf(gh, 1e-12f) / ah);
                tcls = (int)straw[tid * 5];
            } else {
                sflat[tid] = -1;
            }
        }
        __syncthreads();

        if (tid < MAXGT && valid) {
            // last-write-wins: skip if a later valid GT writes the same cell
            bool skip = false;
            int myflat = sflat[tid];
            for (int g2 = tid + 1; g2 < MAXGT; ++g2)
                if (sflat[g2] == myflat) skip = true;

            if (!skip) {
                int i = myflat & 63;
                int j = (myflat >> 6) & 63;
                int a = best;
                int base = ((b * CH + a * (5 + NCLS)) * NH + j) * NW + i;

                float o0 = out[base];
                float o1 = out[base + SPLANE];
                float o2 = out[base + 2 * SPLANE];
                float o3 = out[base + 3 * SPLANE];
                float o4 = out[base + 4 * SPLANE];
                float x = sigm(o0), y = sigm(o1), w = o2, h = o3, conf = sigm(o4);

                float aw = sanc[2 * a], ah = sanc[2 * a + 1];
                float px = x + (float)i, py = y + (float)j;
                float pw = expf(w) * aw, ph = expf(h) * ah;
                float px1 = px - pw * 0.5f, py1 = py - ph * 0.5f;
                float px2 = px + pw * 0.5f, py2 = py + ph * 0.5f;
                float parea = pw * ph;
                float p6 = SIL_T * parea;

                bool over = false;
                for (int g = 0; g < cnt; ++g) {
                    const float* bxp = &sbox[g * 5];
                    float iw = fmaxf(fminf(px2, bxp[2]) - fmaxf(px1, bxp[0]), 0.0f);
                    float ih = fmaxf(fminf(py2, bxp[3]) - fmaxf(py1, bxp[1]), 0.0f);
                    float inter = iw * ih;
                    over |= (1.0f + SIL_T) * inter > (p6 + bxp[4]);
                }
                float cmb = over ? 0.0f : 1.0f;

                // iou of predicted box at this cell vs THIS gt box (precise)
                float iou_best = iou_corners(px1, py1, px2, py2, parea,
                                             gx - gw * 0.5f, gy - gh * 0.5f,
                                             gx + gw * 0.5f, gy + gh * 0.5f, gw * gh);

                float d = 0.0f, e;
                e = x - txv;       d += 0.5f * e * e;
                e = x - 0.5f;      d -= 0.5f * e * e;
                e = y - tyv;       d += 0.5f * e * e;
                e = y - 0.5f;      d -= 0.5f * e * e;
                e = w - twv;       d += 0.5f * e * e;  d -= 0.5f * w * w;
                e = h - thv;       d += 0.5f * e * e;  d -= 0.5f * h * h;
                e = conf - iou_best; d += 0.5f * 5.0f * e * e;
                d -= 0.5f * cmb * conf * conf;

                // class NLL
                float mx = -1e30f;
                #pragma unroll
                for (int c = 0; c < NCLS; ++c)
                    mx = fmaxf(mx, out[base + (5 + c) * SPLANE]);
                float s = 0.0f;
                #pragma unroll
                for (int c = 0; c < NCLS; ++c)
                    s += expf(out[base + (5 + c) * SPLANE] - mx);
                d += mx + logf(s) - out[base + (5 + tcls) * SPLANE];

                local = d;
            }
        }
    }

    // ---- block reduction (float) -> one double partial per block ----
    for (int off = 16; off > 0; off >>= 1)
        local += __shfl_down_sync(0xffffffffu, local, off);
    if (lane == 0) ssum[wid] = local;
    __syncthreads();
    if (tid < 8) {
        float v = ssum[tid];
        for (int off = 4; off > 0; off >>= 1)
            v += __shfl_down_sync(0xffu, v, off);
        if (tid == 0) g_part[b * BX + bx] = (double)v;
    }

    // ---- last-block-done final reduction (single-launch, replay-safe) ----
    if (tid == 0) {
        __threadfence();
        unsigned v = atomicAdd(&g_counter, 1u);
        isLast = (v == NBLOCKS - 1);
    }
    __syncthreads();
    if (isLast) {
        __threadfence();
        double s = 0.0;
        for (int k = tid; k < NBLOCKS; k += 256)
            s += __ldcg(&g_part[k]);
        for (int off = 16; off > 0; off >>= 1)
            s += __shfl_down_sync(0xffffffffu, s, off);
        if (lane == 0) dsum[wid] = s;
        __syncthreads();
        if (tid < 8) {
            double v2 = dsum[tid];
            for (int off = 4; off > 0; off >>= 1)
                v2 += __shfl_down_sync(0xffu, v2, off);
            if (tid == 0) {
                res[0] = (float)v2;
                g_counter = 0;   // reset for next graph replay
            }
        }
    }
}

extern "C" void kernel_launch(void* const* d_in, const int* in_sizes, int n_in,
                              void* d_out, int out_size) {
    const float* out = (const float*)d_in[0];
    const float* tgt = (const float*)d_in[1];
    const float* anc = (const float*)d_in[2];

    dim3 grid(BX, NB);
    yolo_fused<<<grid, 256>>>(out, tgt, anc, (float*)d_out);
}

// round 7
// speedup vs baseline: 3.9067x; 1.0453x over previous
#include <cuda_runtime.h>
#include <math.h>

// Problem constants (fixed by the reference setup_inputs)
#define NB 16
#define NA 5
#define NCLS 20
#define NH 64
#define NW 64
#define MAXGT 50
#define CH (NA * (5 + NCLS))       // 125
#define SPLANE (NH * NW)           // 4096
#define SIL_T 0.6f
#define NCB 10                     // 20480 units / 256 threads (8 cells/thread)
#define BX (NCB + 1)               // 11 (last column: GT-correction work)
#define NBLOCKS (BX * NB)          // 176

__device__ double   g_acc = 0.0;
__device__ unsigned g_counter = 0;

__device__ __forceinline__ float tanh_fast(float v) {
    float r;
    asm("tanh.approx.f32 %0, %1;" : "=f"(r) : "f"(v));
    return r;
}
// sigmoid(v) = 0.5*tanh(v/2) + 0.5   (1 MUFU + 2 FMA)
__device__ __forceinline__ float sigm_fast(float v) {
    return fmaf(0.5f, tanh_fast(0.5f * v), 0.5f);
}
__device__ __forceinline__ float sigm(float v) { return 1.0f / (1.0f + expf(-v)); }

__device__ __forceinline__ float iou_corners(float px1, float py1, float px2, float py2, float parea,
                                             float bx1, float by1, float bx2, float by2, float barea) {
    float iw = fmaxf(fminf(px2, bx2) - fmaxf(px1, bx1), 0.0f);
    float ih = fmaxf(fminf(py2, by2) - fmaxf(py1, by1), 0.0f);
    float inter = iw * ih;
    float uni = parea + barea - inter;
    return uni > 0.0f ? inter / uni : 0.0f;
}

__global__ __launch_bounds__(256) void yolo_fused(const float* __restrict__ out,
                                                  const float* __restrict__ tgt,
                                                  const float* __restrict__ anc,
                                                  float* __restrict__ res) {
    __shared__ float sbox[MAXGT * 5];   // compacted: x1,y1,x2,y2, 0.6*area
    __shared__ int   scnt;
    __shared__ float ssum[8];
    __shared__ int   sflat[MAXGT];
    __shared__ bool  isLast;

    const int b = blockIdx.y;
    const int bx = blockIdx.x;
    const int tid = threadIdx.x;
    const int lane = tid & 31;
    const int wid = tid >> 5;

    // ====== prefetch main-plane loads + anchors (independent of tgt) ======
    float4 o0a, o0b, o1a, o1b, o2a, o2b, o3a, o3b, o4a, o4b;
    float aw_ = 0.f, ah_ = 0.f;
    int j_ = 0, i0_ = 0;
    if (bx < NCB) {
        int unit = bx * 256 + tid;       // 8 consecutive cells per unit
        int a_ = unit >> 9;              // 512 units per anchor plane
        int rem = unit & 511;
        j_ = rem >> 3;
        i0_ = (rem & 7) * 8;
        int base = ((b * CH + a_ * (5 + NCLS)) * NH + j_) * NW + i0_;
        o0a = *(const float4*)(out + base);
        o0b = *(const float4*)(out + base + 4);
        o1a = *(const float4*)(out + base + SPLANE);
        o1b = *(const float4*)(out + base + SPLANE + 4);
        o2a = *(const float4*)(out + base + 2 * SPLANE);
        o2b = *(const float4*)(out + base + 2 * SPLANE + 4);
        o3a = *(const float4*)(out + base + 3 * SPLANE);
        o3b = *(const float4*)(out + base + 3 * SPLANE + 4);
        o4a = *(const float4*)(out + base + 4 * SPLANE);
        o4b = *(const float4*)(out + base + 4 * SPLANE + 4);
        aw_ = __ldg(&anc[2 * a_]);
        ah_ = __ldg(&anc[2 * a_ + 1]);
    }

    // ====== GT preprocessing: warp 0 only, direct gmem, ONE barrier =======
    if (wid == 0) {
        const float* tb = tgt + b * MAXGT * 5;
        // slot A = lane (0..31), slot B = 32+lane (lane<18)
        float a1 = tb[lane * 5 + 1];
        float a2 = tb[lane * 5 + 2];
        float a3 = tb[lane * 5 + 3];
        float a4 = tb[lane * 5 + 4];
        bool vA = (a1 > 0.0f);
        float c1 = 0.f, c2 = 0.f, c3 = 0.f, c4 = 0.f;
        bool vB = false;
        if (lane < MAXGT - 32) {
            int s = 32 + lane;
            c1 = tb[s * 5 + 1]; c2 = tb[s * 5 + 2];
            c3 = tb[s * 5 + 3]; c4 = tb[s * 5 + 4];
            vB = (c1 > 0.0f);
        }
        unsigned mA = __ballot_sync(0xffffffffu, vA);
        unsigned mB = __ballot_sync(0xffffffffu, vB);
        int cA = __popc(mA);
        if (vA) {
            int idx = __popc(mA & ((1u << lane) - 1u));
            float gx = a1 * NW, gy = a2 * NH, gw = a3 * NW, gh = a4 * NH;
            float* p = &sbox[idx * 5];
            p[0] = gx - gw * 0.5f; p[1] = gy - gh * 0.5f;
            p[2] = gx + gw * 0.5f; p[3] = gy + gh * 0.5f;
            p[4] = SIL_T * (gw * gh);
        }
        if (vB) {
            int idx = cA + __popc(mB & ((1u << lane) - 1u));
            float gx = c1 * NW, gy = c2 * NH, gw = c3 * NW, gh = c4 * NH;
            float* p = &sbox[idx * 5];
            p[0] = gx - gw * 0.5f; p[1] = gy - gh * 0.5f;
            p[2] = gx + gw * 0.5f; p[3] = gy + gh * 0.5f;
            p[4] = SIL_T * (gw * gh);
        }
        if (lane == 0) scnt = cA + __popc(mB);
    }
    __syncthreads();
    const int cnt = scnt;

    float local = 0.0f;

    if (bx < NCB) {
        const float fj = (float)j_;

        float xs[8] = {sigm_fast(o0a.x), sigm_fast(o0a.y), sigm_fast(o0a.z), sigm_fast(o0a.w),
                       sigm_fast(o0b.x), sigm_fast(o0b.y), sigm_fast(o0b.z), sigm_fast(o0b.w)};
        float ys[8] = {sigm_fast(o1a.x), sigm_fast(o1a.y), sigm_fast(o1a.z), sigm_fast(o1a.w),
                       sigm_fast(o1b.x), sigm_fast(o1b.y), sigm_fast(o1b.z), sigm_fast(o1b.w)};
        float ws[8] = {o2a.x, o2a.y, o2a.z, o2a.w, o2b.x, o2b.y, o2b.z, o2b.w};
        float hs[8] = {o3a.x, o3a.y, o3a.z, o3a.w, o3b.x, o3b.y, o3b.z, o3b.w};
        float cs[8] = {sigm_fast(o4a.x), sigm_fast(o4a.y), sigm_fast(o4a.z), sigm_fast(o4a.w),
                       sigm_fast(o4b.x), sigm_fast(o4b.y), sigm_fast(o4b.z), sigm_fast(o4b.w)};

        float px1[8], py1[8], px2[8], py2[8], p6[8], mi[8];
        #pragma unroll
        for (int c = 0; c < 8; ++c) {
            float px = xs[c] + (float)(i0_ + c);
            float py = ys[c] + fj;
            float pw = __expf(ws[c]) * aw_;
            float ph = __expf(hs[c]) * ah_;
            px1[c] = px - pw * 0.5f; py1[c] = py - ph * 0.5f;
            px2[c] = px + pw * 0.5f; py2[c] = py + ph * 0.5f;
            p6[c]  = SIL_T * (pw * ph);
            mi[c]  = -1e30f;          // running max of 1.6*inter - 0.6*barea
        }

        for (int g = 0; g < cnt; ++g) {
            const float bx1 = sbox[g * 5 + 0];
            const float by1 = sbox[g * 5 + 1];
            const float bx2 = sbox[g * 5 + 2];
            const float by2 = sbox[g * 5 + 3];
            const float b6  = sbox[g * 5 + 4];
            #pragma unroll
            for (int c = 0; c < 8; ++c) {
                float iw = fmaxf(fminf(px2[c], bx2) - fmaxf(px1[c], bx1), 0.0f);
                float ih = fmaxf(fminf(py2[c], by2) - fmaxf(py1[c], by1), 0.0f);
                // max_iou > 0.6  <=>  max_g (1.6*inter - 0.6*barea) > 0.6*parea
                mi[c] = fmaxf(mi[c], fmaf((1.0f + SIL_T), iw * ih, -b6));
            }
        }

        #pragma unroll
        for (int c = 0; c < 8; ++c) {
            float dx = xs[c] - 0.5f, dy = ys[c] - 0.5f;
            float cmb = (mi[c] > p6[c]) ? 0.0f : 1.0f;
            local += 0.5f * (dx * dx + dy * dy + ws[c] * ws[c] + hs[c] * hs[c])
                   + 0.5f * cmb * cs[c] * cs[c];
        }
    } else {
        // ---- per-GT correction terms (one thread per GT slot) ----
        int best = 0;
        float txv = 0.f, tyv = 0.f, twv = 0.f, thv = 0.f;
        int tcls = 0;
        bool valid = false;
        float gx = 0.f, gy = 0.f, gw = 0.f, gh = 0.f;

        if (tid < MAXGT) {
            const float* t = tgt + (b * MAXGT + tid) * 5;
            float t0 = t[0], t1 = t[1], t2 = t[2], t3 = t[3], t4 = t[4];
            valid = (t1 > 0.0f);
            if (valid) {
                gx = t1 * NW; gy = t2 * NH; gw = t3 * NW; gh = t4 * NH;
                float bestiou = -1.0f;
                for (int a = 0; a < NA; ++a) {
                    float aw = __ldg(&anc[2 * a]), ah = __ldg(&anc[2 * a + 1]);
                    float inter = fminf(gw, aw) * fminf(gh, ah);
                    float uni = gw * gh + aw * ah - inter;
                    float io = uni > 0.0f ? inter / uni : 0.0f;
                    if (io > bestiou) { bestiou = io; best = a; }
                }
                int gi = min(max((int)gx, 0), NW - 1);
                int gj = min(max((int)gy, 0), NH - 1);
                sflat[tid] = ((b * NA + best) * NH + gj) * NW + gi;
                float aw = __ldg(&anc[2 * best]), ah = __ldg(&anc[2 * best + 1]);
                txv = gx - (float)gi;
                tyv = gy - (float)gj;
                twv = logf(fmaxf(gw, 1e-12f) / aw);
                thv = logf(fmaxf(gh, 1e-12f) / ah);
                tcls = (int)t0;
            } else {
                sflat[tid] = -1;
            }
        }
        __syncthreads();

        if (tid < MAXGT && valid) {
            // last-write-wins: skip if a later valid GT writes the same cell
            bool skip = false;
            int myflat = sflat[tid];
            for (int g2 = tid + 1; g2 < MAXGT; ++g2)
                if (sflat[g2] == myflat) skip = true;

            if (!skip) {
                int i = myflat & 63;
                int j = (myflat >> 6) & 63;
                int a = best;
                int base = ((b * CH + a * (5 + NCLS)) * NH + j) * NW + i;

                float o0 = out[base];
                float o1 = out[base + SPLANE];
                float o2 = out[base + 2 * SPLANE];
                float o3 = out[base + 3 * SPLANE];
                float o4 = out[base + 4 * SPLANE];
                float x = sigm(o0), y = sigm(o1), w = o2, h = o3, conf = sigm(o4);

                float aw = __ldg(&anc[2 * a]), ah = __ldg(&anc[2 * a + 1]);
                float px = x + (float)i, py = y + (float)j;
                float pw = expf(w) * aw, ph = expf(h) * ah;
                float px1 = px - pw * 0.5f, py1 = py - ph * 0.5f;
                float px2 = px + pw * 0.5f, py2 = py + ph * 0.5f;
                float parea = pw * ph;
                float p6 = SIL_T * parea;

                bool over = false;
                for (int g = 0; g < cnt; ++g) {
                    const float* bxp = &sbox[g * 5];
                    float iw = fmaxf(fminf(px2, bxp[2]) - fmaxf(px1, bxp[0]), 0.0f);
                    float ih = fmaxf(fminf(py2, bxp[3]) - fmaxf(py1, bxp[1]), 0.0f);
                    float inter = iw * ih;
                    over |= (1.0f + SIL_T) * inter > (p6 + bxp[4]);
                }
                float cmb = over ? 0.0f : 1.0f;

                // iou of predicted box at this cell vs THIS gt box (precise)
                float iou_best = iou_corners(px1, py1, px2, py2, parea,
                                             gx - gw * 0.5f, gy - gh * 0.5f,
                                             gx + gw * 0.5f, gy + gh * 0.5f, gw * gh);

                float d = 0.0f, e;
                e = x - txv;       d += 0.5f * e * e;
                e = x - 0.5f;      d -= 0.5f * e * e;
                e = y - tyv;       d += 0.5f * e * e;
                e = y - 0.5f;      d -= 0.5f * e * e;
                e = w - twv;       d += 0.5f * e * e;  d -= 0.5f * w * w;
                e = h - thv;       d += 0.5f * e * e;  d -= 0.5f * h * h;
                e = conf - iou_best; d += 0.5f * 5.0f * e * e;
                d -= 0.5f * cmb * conf * conf;

                // class NLL
                float mx = -1e30f;
                #pragma unroll
                for (int c = 0; c < NCLS; ++c)
                    mx = fmaxf(mx, out[base + (5 + c) * SPLANE]);
                float s = 0.0f;
                #pragma unroll
                for (int c = 0; c < NCLS; ++c)
                    s += expf(out[base + (5 + c) * SPLANE] - mx);
                d += mx + logf(s) - out[base + (5 + tcls) * SPLANE];

                local = d;
            }
        }
    }

    // ---- block reduction (float), then ONE double atomic per block ----
    for (int off = 16; off > 0; off >>= 1)
        local += __shfl_down_sync(0xffffffffu, local, off);
    if (lane == 0) ssum[wid] = local;
    __syncthreads();
    if (tid == 0) {
        float v = ssum[0];
        #pragma unroll
        for (int k = 1; k < 8; ++k) v += ssum[k];
        atomicAdd(&g_acc, (double)v);
        __threadfence();
        unsigned c = atomicAdd(&g_counter, 1u);
        isLast = (c == NBLOCKS - 1);
    }
    __syncthreads();
    if (isLast && tid == 0) {
        __threadfence();
        double total = *((volatile double*)&g_acc);
        res[0] = (float)total;
        g_acc = 0.0;        // reset for next graph replay
        g_counter = 0;
    }
}

extern "C" void kernel_launch(void* const* d_in, const int* in_sizes, int n_in,
                              void* d_out, int out_size) {
    const float* out = (const float*)d_in[0];
    const float* tgt = (const float*)d_in[1];
    const float* anc = (const float*)d_in[2];

    dim3 grid(BX, NB);
    yolo_fused<<<grid, 256>>>(out, tgt, anc, (float*)d_out);
}

// round 8
// speedup vs baseline: 4.4260x; 1.1329x over previous
#include <cuda_runtime.h>
#include <math.h>

// Problem constants (fixed by the reference setup_inputs)
#define NB 16
#define NA 5
#define NCLS 20
#define NH 64
#define NW 64
#define MAXGT 50
#define CH (NA * (5 + NCLS))       // 125
#define SPLANE (NH * NW)           // 4096
#define SIL_T 0.6f

#define CELLBLK 8                  // cell blocks per batch
#define UNITS_PER_BLK 640          // float4-units per cell block (5120/8)
#define BXDIM (CELLBLK + 1)        // 9 (last column: GT-correction)
#define NBLOCKS (BXDIM * NB)       // 144  (<= 148 SMs: one balanced wave)

__device__ double   g_acc = 0.0;
__device__ unsigned g_counter = 0;

__device__ __forceinline__ float tanh_fast(float v) {
    float r;
    asm("tanh.approx.f32 %0, %1;" : "=f"(r) : "f"(v));
    return r;
}
// sigmoid(v) = 0.5*tanh(v/2) + 0.5   (1 MUFU + 2 FMA)
__device__ __forceinline__ float sigm_fast(float v) {
    return fmaf(0.5f, tanh_fast(0.5f * v), 0.5f);
}
__device__ __forceinline__ float sigm(float v) { return 1.0f / (1.0f + expf(-v)); }

__device__ __forceinline__ float iou_corners(float px1, float py1, float px2, float py2, float parea,
                                             float bx1, float by1, float bx2, float by2, float barea) {
    float iw = fmaxf(fminf(px2, bx2) - fmaxf(px1, bx1), 0.0f);
    float ih = fmaxf(fminf(py2, by2) - fmaxf(py1, by1), 0.0f);
    float inter = iw * ih;
    float uni = parea + barea - inter;
    return uni > 0.0f ? inter / uni : 0.0f;
}

__device__ __forceinline__ void load_unit(const float* __restrict__ out, int b, int u,
                                          int& a, int& j, int& i0, float4 L[5]) {
    a = u >> 10;                 // 1024 float4-units per anchor plane
    int rem = u & 1023;
    j = rem >> 4;
    i0 = (rem & 15) * 4;
    int base = ((b * CH + a * (5 + NCLS)) * NH + j) * NW + i0;
    L[0] = *(const float4*)(out + base);
    L[1] = *(const float4*)(out + base + SPLANE);
    L[2] = *(const float4*)(out + base + 2 * SPLANE);
    L[3] = *(const float4*)(out + base + 3 * SPLANE);
    L[4] = *(const float4*)(out + base + 4 * SPLANE);
}

__global__ __launch_bounds__(256) void yolo_fused(const float* __restrict__ out,
                                                  const float* __restrict__ tgt,
                                                  const float* __restrict__ anc,
                                                  float* __restrict__ res) {
    __shared__ float4 sboxv[MAXGT];   // compacted GT corners x1,y1,x2,y2
    __shared__ float  sb6[MAXGT];     // 0.6 * area
    __shared__ int    scnt;
    __shared__ float  ssum[8];
    __shared__ int    sflat[MAXGT];
    __shared__ bool   isLast;

    const int b = blockIdx.y;
    const int bx = blockIdx.x;
    const int tid = threadIdx.x;
    const int lane = tid & 31;
    const int wid = tid >> 5;
    const bool cellBlock = (bx < CELLBLK);

    // ====== prefetch first unit (independent of tgt) ======
    float4 L0[5];
    int a0 = 0, j0 = 0, i00 = 0;
    int u = 0, uend = 0;
    if (cellBlock) {
        u = bx * UNITS_PER_BLK + tid;
        uend = (bx + 1) * UNITS_PER_BLK;
        load_unit(out, b, u, a0, j0, i00, L0);   // u < uend always (tid < 256 < 640)
    }

    // ====== GT preprocessing: warp 0 only, ONE barrier ======
    if (wid == 0) {
        const float* tb = tgt + b * MAXGT * 5;
        float a1 = tb[lane * 5 + 1];
        float a2 = tb[lane * 5 + 2];
        float a3 = tb[lane * 5 + 3];
        float a4 = tb[lane * 5 + 4];
        bool vA = (a1 > 0.0f);
        float c1 = 0.f, c2 = 0.f, c3 = 0.f, c4 = 0.f;
        bool vB = false;
        if (lane < MAXGT - 32) {
            int s = 32 + lane;
            c1 = tb[s * 5 + 1]; c2 = tb[s * 5 + 2];
            c3 = tb[s * 5 + 3]; c4 = tb[s * 5 + 4];
            vB = (c1 > 0.0f);
        }
        unsigned mA = __ballot_sync(0xffffffffu, vA);
        unsigned mB = __ballot_sync(0xffffffffu, vB);
        int cA = __popc(mA);
        if (vA) {
            int idx = __popc(mA & ((1u << lane) - 1u));
            float gx = a1 * NW, gy = a2 * NH, gw = a3 * NW, gh = a4 * NH;
            sboxv[idx] = make_float4(gx - gw * 0.5f, gy - gh * 0.5f,
                                     gx + gw * 0.5f, gy + gh * 0.5f);
            sb6[idx] = SIL_T * (gw * gh);
        }
        if (vB) {
            int idx = cA + __popc(mB & ((1u << lane) - 1u));
            float gx = c1 * NW, gy = c2 * NH, gw = c3 * NW, gh = c4 * NH;
            sboxv[idx] = make_float4(gx - gw * 0.5f, gy - gh * 0.5f,
                                     gx + gw * 0.5f, gy + gh * 0.5f);
            sb6[idx] = SIL_T * (gw * gh);
        }
        if (lane == 0) scnt = cA + __popc(mB);
    }
    __syncthreads();
    const int cnt = scnt;

    float local = 0.0f;

    if (cellBlock) {
        // ---- pipelined unit loop: load next while processing current ----
        while (true) {
            int un = u + 256;
            bool hasNext = (un < uend);
            float4 L1[5];
            int a1_ = 0, j1_ = 0, i01_ = 0;
            if (hasNext) load_unit(out, b, un, a1_, j1_, i01_, L1);

            // process current unit (4 cells)
            {
                const float aw = __ldg(&anc[2 * a0]);
                const float ah = __ldg(&anc[2 * a0 + 1]);
                const float fj = (float)j0;

                float xs[4] = {sigm_fast(L0[0].x), sigm_fast(L0[0].y), sigm_fast(L0[0].z), sigm_fast(L0[0].w)};
                float ys[4] = {sigm_fast(L0[1].x), sigm_fast(L0[1].y), sigm_fast(L0[1].z), sigm_fast(L0[1].w)};
                float ws[4] = {L0[2].x, L0[2].y, L0[2].z, L0[2].w};
                float hs[4] = {L0[3].x, L0[3].y, L0[3].z, L0[3].w};
                float cs[4] = {sigm_fast(L0[4].x), sigm_fast(L0[4].y), sigm_fast(L0[4].z), sigm_fast(L0[4].w)};

                float px1[4], py1[4], px2[4], py2[4], p6[4], mi[4];
                #pragma unroll
                for (int c = 0; c < 4; ++c) {
                    float px = xs[c] + (float)(i00 + c);
                    float py = ys[c] + fj;
                    float pw = __expf(ws[c]) * aw;
                    float ph = __expf(hs[c]) * ah;
                    px1[c] = px - pw * 0.5f; py1[c] = py - ph * 0.5f;
                    px2[c] = px + pw * 0.5f; py2[c] = py + ph * 0.5f;
                    p6[c]  = SIL_T * (pw * ph);
                    mi[c]  = -1e30f;      // running max of 1.6*inter - 0.6*barea
                }

                for (int g = 0; g < cnt; ++g) {
                    float4 bv = sboxv[g];
                    float b6 = sb6[g];
                    #pragma unroll
                    for (int c = 0; c < 4; ++c) {
                        float iw = fmaxf(fminf(px2[c], bv.z) - fmaxf(px1[c], bv.x), 0.0f);
                        float ih = fmaxf(fminf(py2[c], bv.w) - fmaxf(py1[c], bv.y), 0.0f);
                        // max_iou > 0.6 <=> max_g(1.6*inter - 0.6*barea) > 0.6*parea
                        mi[c] = fmaxf(mi[c], fmaf((1.0f + SIL_T), iw * ih, -b6));
                    }
                }

                #pragma unroll
                for (int c = 0; c < 4; ++c) {
                    float dx = xs[c] - 0.5f, dy = ys[c] - 0.5f;
                    float cmb = (mi[c] > p6[c]) ? 0.0f : 1.0f;
                    local += 0.5f * (dx * dx + dy * dy + ws[c] * ws[c] + hs[c] * hs[c])
                           + 0.5f * cmb * cs[c] * cs[c];
                }
            }

            if (!hasNext) break;
            u = un;
            a0 = a1_; j0 = j1_; i00 = i01_;
            #pragma unroll
            for (int k = 0; k < 5; ++k) L0[k] = L1[k];
        }
    } else {
        // ---- per-GT correction terms (one thread per GT slot) ----
        int best = 0;
        float txv = 0.f, tyv = 0.f, twv = 0.f, thv = 0.f;
        int tcls = 0;
        bool valid = false;
        float gx = 0.f, gy = 0.f, gw = 0.f, gh = 0.f;

        if (tid < MAXGT) {
            const float* t = tgt + (b * MAXGT + tid) * 5;
            float t0 = t[0], t1 = t[1], t2 = t[2], t3 = t[3], t4 = t[4];
            valid = (t1 > 0.0f);
            if (valid) {
                gx = t1 * NW; gy = t2 * NH; gw = t3 * NW; gh = t4 * NH;
                float bestiou = -1.0f;
                for (int a = 0; a < NA; ++a) {
                    float aw = __ldg(&anc[2 * a]), ah = __ldg(&anc[2 * a + 1]);
                    float inter = fminf(gw, aw) * fminf(gh, ah);
                    float uni = gw * gh + aw * ah - inter;
                    float io = uni > 0.0f ? inter / uni : 0.0f;
                    if (io > bestiou) { bestiou = io; best = a; }
                }
                int gi = min(max((int)gx, 0), NW - 1);
                int gj = min(max((int)gy, 0), NH - 1);
                sflat[tid] = ((b * NA + best) * NH + gj) * NW + gi;
                float aw = __ldg(&anc[2 * best]), ah = __ldg(&anc[2 * best + 1]);
                txv = gx - (float)gi;
                tyv = gy - (float)gj;
                twv = logf(fmaxf(gw, 1e-12f) / aw);
                thv = logf(fmaxf(gh, 1e-12f) / ah);
                tcls = (int)t0;
            } else {
                sflat[tid] = -1;
            }
        }
        __syncthreads();

        if (tid < MAXGT && valid) {
            // last-write-wins: skip if a later valid GT writes the same cell
            bool skip = false;
            int myflat = sflat[tid];
            for (int g2 = tid + 1; g2 < MAXGT; ++g2)
                if (sflat[g2] == myflat) skip = true;

            if (!skip) {
                int i = myflat & 63;
                int j = (myflat >> 6) & 63;
                int a = best;
                int base = ((b * CH + a * (5 + NCLS)) * NH + j) * NW + i;

                float o0 = out[base];
                float o1 = out[base + SPLANE];
                float o2 = out[base + 2 * SPLANE];
                float o3 = out[base + 3 * SPLANE];
                float o4 = out[base + 4 * SPLANE];
                float x = sigm(o0), y = sigm(o1), w = o2, h = o3, conf = sigm(o4);

                float aw = __ldg(&anc[2 * a]), ah = __ldg(&anc[2 * a + 1]);
                float px = x + (float)i, py = y + (float)j;
                float pw = expf(w) * aw, ph = expf(h) * ah;
                float px1 = px - pw * 0.5f, py1 = py - ph * 0.5f;
                float px2 = px + pw * 0.5f, py2 = py + ph * 0.5f;
                float parea = pw * ph;
                float p6 = SIL_T * parea;

                bool over = false;
                for (int g = 0; g < cnt; ++g) {
                    float4 bv = sboxv[g];
                    float iw = fmaxf(fminf(px2, bv.z) - fmaxf(px1, bv.x), 0.0f);
                    float ih = fmaxf(fminf(py2, bv.w) - fmaxf(py1, bv.y), 0.0f);
                    over |= (1.0f + SIL_T) * (iw * ih) > (p6 + sb6[g]);
                }
                float cmb = over ? 0.0f : 1.0f;

                // iou of predicted box at this cell vs THIS gt box (precise)
                float iou_best = iou_corners(px1, py1, px2, py2, parea,
                                             gx - gw * 0.5f, gy - gh * 0.5f,
                                             gx + gw * 0.5f, gy + gh * 0.5f, gw * gh);

                float d = 0.0f, e;
                e = x - txv;       d += 0.5f * e * e;
                e = x - 0.5f;      d -= 0.5f * e * e;
                e = y - tyv;       d += 0.5f * e * e;
                e = y - 0.5f;      d -= 0.5f * e * e;
                e = w - twv;       d += 0.5f * e * e;  d -= 0.5f * w * w;
                e = h - thv;       d += 0.5f * e * e;  d -= 0.5f * h * h;
                e = conf - iou_best; d += 0.5f * 5.0f * e * e;
                d -= 0.5f * cmb * conf * conf;

                // class NLL
                float mx = -1e30f;
                #pragma unroll
                for (int c = 0; c < NCLS; ++c)
                    mx = fmaxf(mx, out[base + (5 + c) * SPLANE]);
                float s = 0.0f;
                #pragma unroll
                for (int c = 0; c < NCLS; ++c)
                    s += expf(out[base + (5 + c) * SPLANE] - mx);
                d += mx + logf(s) - out[base + (5 + tcls) * SPLANE];

                local = d;
            }
        }
    }

    // ---- block reduction (float), then ONE double atomic per block ----
    for (int off = 16; off > 0; off >>= 1)
        local += __shfl_down_sync(0xffffffffu, local, off);
    if (lane == 0) ssum[wid] = local;
    __syncthreads();
    if (tid == 0) {
        float v = ssum[0];
        #pragma unroll
        for (int k = 1; k < 8; ++k) v += ssum[k];
        atomicAdd(&g_acc, (double)v);
        __threadfence();
        unsigned c = atomicAdd(&g_counter, 1u);
        isLast = (c == NBLOCKS - 1);
    }
    __syncthreads();
    if (isLast && tid == 0) {
        __threadfence();
        double total = *((volatile double*)&g_acc);
        res[0] = (float)total;
        g_acc = 0.0;        // reset for next graph replay
        g_counter = 0;
    }
}

extern "C" void kernel_launch(void* const* d_in, const int* in_sizes, int n_in,
                              void* d_out, int out_size) {
    const float* out = (const float*)d_in[0];
    const float* tgt = (const float*)d_in[1];
    const float* anc = (const float*)d_in[2];

    dim3 grid(BXDIM, NB);
    yolo_fused<<<grid, 256>>>(out, tgt, anc, (float*)d_out);
}